// round 17
// baseline (speedup 1.0000x reference)
#include <cuda_runtime.h>
#include <cstdint>

// Problem constants (from reference)
#define F 8
#define B 4096
#define V 100000
#define D 128
#define NVALS 81920
#define CHUNK 32
#define CPF (NVALS / CHUNK)   // 2560 chunks per feature (divisible by WPB)
#define STAGES 8              // per-warp smem pipeline depth (rows in flight)
#define WPB 8                 // warps per block
#define TPB (WPB * 32)        // 256 threads: block covers 256 consecutive positions

template<int N>
__device__ __forceinline__ void cp_wait() {
    asm volatile("cp.async.wait_group %0;" :: "n"(N) : "memory");
}

// One warp per 32-value chunk (perfectly balanced). Row gathers staged through
// a per-warp 8-deep SMEM ring via cp.async. Bag ids computed block-
// cooperatively: warp 0 finds s0 with a 3-level warp-parallel 32-ary search,
// then one coalesced 257-boundary load into smem + per-thread 9-iter LDS
// upper_bound. Segment transitions precomputed into one ballot mask (SHFL
// only on actual transitions). Steady state consumes TWO rows per wait
// (wait_group 6 retires the two oldest groups) halving the wait/branch count
// in the pacing recurrence. Partial bag sums flushed with
// red.global.add.v4.f32 (output pre-zeroed by the memset node).
__global__ __launch_bounds__(TPB)
void ebc_chunk_kernel(const int* __restrict__ values,    // [F, NVALS]
                      const int* __restrict__ offsets,   // [F, B+1]
                      const float* __restrict__ tables,  // [F, V, D]
                      float* __restrict__ out)           // [B, F*D]
{
    __shared__ float4 sbuf[WPB][STAGES][32];   // 32 KB gather ring
    __shared__ int sb[TPB + 1];                // boundaries offs[s0+1..s0+256] + sentinel
    __shared__ int s_s0;

    const int wib   = threadIdx.x >> 5;
    const int lane  = threadIdx.x & 31;
    const int gwarp = blockIdx.x * WPB + wib;

    // f-major: all warps of a block share one feature/table (L2 locality)
    const int f = gwarp / CPF;
    const int c = gwarp - f * CPF;
    const int pos = c * CHUNK + lane;          // this lane's value position

    const int myidx = __ldg(values + (size_t)f * NVALS + pos);

    const float4* tab = reinterpret_cast<const float4*>(tables)
                        + (size_t)f * V * (D / 4) + lane;

    const uint32_t sbase =
        (uint32_t)__cvta_generic_to_shared(&sbuf[wib][0][lane]);

    // issue row r's 512B gather into stage r % STAGES (one 16B cp.async/lane)
    auto issue = [&](int r) {
        const int row = __shfl_sync(0xffffffffu, myidx, r);
        const float4* src = tab + (size_t)row * (D / 4);
        const uint32_t dst = sbase + (uint32_t)((r & (STAGES - 1)) * 32) * 16u;
        asm volatile("cp.async.cg.shared.global [%0], [%1], 16;\n\t"
                     "cp.async.commit_group;"
                     :: "r"(dst), "l"(src) : "memory");
    };

    // prologue: fill the ring FIRST; the segment lookup hides under it
    #pragma unroll
    for (int r = 0; r < STAGES; ++r) issue(r);

    // ---- block-cooperative segment lookup ----
    const int* offs = offsets + f * (B + 1);
    const int P0 = ((blockIdx.x * WPB) - f * CPF) * CHUNK;  // block's first position

    if (wib == 0) {
        // s0 = largest j in [0, B-1] with offs[j] <= P0, via 3-level 32-ary
        // warp-parallel search (offs[0]=0 <= P0 always -> ballots nonzero).
        unsigned b1 = __ballot_sync(0xffffffffu, __ldg(offs + lane * 128) <= P0);
        int base1 = (31 - __clz(b1)) * 128;                       // 0..3968
        unsigned b2 = __ballot_sync(0xffffffffu, __ldg(offs + base1 + lane * 4) <= P0);
        int base2 = base1 + (31 - __clz(b2)) * 4;                 // 0..4092
        unsigned b3 = __ballot_sync(0xffffffffu, __ldg(offs + base2 + (lane & 3)) <= P0) & 0xFu;
        if (lane == 0) s_s0 = base2 + (31 - __clz(b3));           // 0..4095
    }
    __syncthreads();
    const int s0 = s_s0;

    // coalesced load of the next 256 boundaries (clamped; offs[B]=N > any pos)
    {
        int j = s0 + 1 + threadIdx.x;
        sb[threadIdx.x] = __ldg(offs + (j > B ? B : j));
    }
    if (threadIdx.x == 0) sb[TPB] = 0x7fffffff;   // sentinel
    __syncthreads();

    // cnt = upper_bound(sb[0..255], pos): first index with sb[idx] > pos.
    // Answers in [0,256] (257 values) -> 9 iterations; sentinel keeps
    // post-convergence iterations stable.
    int cnt;
    {
        int lo = 0, hi = TPB;
        #pragma unroll
        for (int it = 0; it < 9; ++it) {
            int mid = (lo + hi) >> 1;
            if (sb[mid] <= pos) lo = mid + 1; else hi = mid;
        }
        cnt = lo;
    }
    int myseg = s0 + cnt;
    if (cnt == TPB) {
        // pathological window (>=256 bags in 256 positions): exact global bsearch
        int lo = 0, hi = B - 1;
        for (int it = 0; it < 12; ++it) {
            int mid = (lo + hi + 1) >> 1;
            if (__ldg(offs + mid) <= pos) lo = mid; else hi = mid - 1;
        }
        myseg = lo;
    }
    // ---- end segment lookup ----

    // Precompute transition mask: bit j set iff seg(pos j) != seg(pos j-1).
    const int segprev = __shfl_up_sync(0xffffffffu, myseg, 1);
    const unsigned tmask =
        __ballot_sync(0xffffffffu, lane > 0 && myseg != segprev);

    float4 acc = make_float4(0.f, 0.f, 0.f, 0.f);
    int cur = __shfl_sync(0xffffffffu, myseg, 0);

    auto flush = [&]() {
        float* o = out + (size_t)cur * (F * D) + f * D + lane * 4;
        asm volatile("red.global.add.v4.f32 [%0], {%1,%2,%3,%4};"
                     :: "l"(o), "f"(acc.x), "f"(acc.y), "f"(acc.z), "f"(acc.w)
                     : "memory");
    };

    auto consume = [&](int j, const float4& v) {
        if (tmask & (1u << j)) {               // warp-uniform immediate test
            flush();
            acc = make_float4(0.f, 0.f, 0.f, 0.f);
            cur = __shfl_sync(0xffffffffu, myseg, j);  // only on transitions
        }
        acc.x += v.x; acc.y += v.y; acc.z += v.z; acc.w += v.w;
    };

    // steady state, pairwise: wait until the two oldest groups retired
    // (<=6 outstanding), read both rows, re-issue both, then accumulate.
    #pragma unroll
    for (int j = 0; j < CHUNK - STAGES; j += 2) {
        cp_wait<STAGES - 2>();
        const float4 v0 = sbuf[wib][j & (STAGES - 1)][lane];
        const float4 v1 = sbuf[wib][(j + 1) & (STAGES - 1)][lane];
        issue(j + STAGES);
        issue(j + STAGES + 1);
        consume(j, v0);
        consume(j + 1, v1);
    }
    // tail: everything issued; drain
    cp_wait<0>();
    #pragma unroll
    for (int j = CHUNK - STAGES; j < CHUNK; ++j) {
        const float4 v = sbuf[wib][j & (STAGES - 1)][lane];
        consume(j, v);
    }

    // final flush
    flush();
}

extern "C" void kernel_launch(void* const* d_in, const int* in_sizes, int n_in,
                              void* d_out, int out_size)
{
    const int*   values  = (const int*)d_in[0];   // [F, NVALS] int32
    const int*   offsets = (const int*)d_in[1];   // [F, B+1] int32
    const float* tables  = (const float*)d_in[2]; // [F, V, D] float32
    float*       out     = (float*)d_out;         // [B, F*D] float32

    // 1) zero the output with a CE memset node (atomics accumulate into it)
    cudaMemsetAsync(out, 0, (size_t)B * F * D * sizeof(float), 0);

    // 2) balanced, smem-pipelined gather + segment-reduce
    const int total_warps = F * CPF;               // 20480
    const int blocks = total_warps / WPB;          // 2560
    ebc_chunk_kernel<<<blocks, TPB>>>(values, offsets, tables, out);
}